// round 2
// baseline (speedup 1.0000x reference)
#include <cuda_runtime.h>
#include <math.h>

#define Bz 8
#define Tz 4096
#define Cz 768
#define Hz 64

// q/k/v scratch (allocation-free rule: __device__ globals)
__device__ float g_q[Bz * Tz * Hz];
__device__ float g_k[Bz * Tz * Hz];
__device__ float g_v[Bz * Tz * Hz];

// ---------------------------------------------------------------------------
// Projection: out[b,t,h] = sum_c x[b,t,c] * W[c,h]
// M = B*T = 32768, K = 768, N = 64. grid = (512, 3): y selects Wq/Wk/Wv.
// 64x64 output tile per block, 256 threads, 4x4 register blocking.
// ---------------------------------------------------------------------------
#define PT_M 64
#define PT_K 32

__global__ void proj_kernel(const float* __restrict__ x,
                            const float* __restrict__ Wk,
                            const float* __restrict__ Wq,
                            const float* __restrict__ Wv) {
    __shared__ float xs[PT_M][PT_K + 1];
    __shared__ float ws[PT_K][Hz + 1];

    int mat = blockIdx.y;
    const float* W = (mat == 0) ? Wq : ((mat == 1) ? Wk : Wv);
    float* out = (mat == 0) ? g_q : ((mat == 1) ? g_k : g_v);

    long row0 = (long)blockIdx.x * PT_M;
    int tid = threadIdx.x;
    int tr = tid / 16;   // row group 0..15  -> rows tr*4 .. tr*4+3
    int tc = tid % 16;   // col group 0..15  -> cols tc*4 .. tc*4+3

    float acc[4][4] = {};

    for (int k0 = 0; k0 < Cz; k0 += PT_K) {
        // stage x tile [64 x 32]
        for (int idx = tid; idx < PT_M * PT_K; idx += 256) {
            int r = idx / PT_K, k = idx % PT_K;
            xs[r][k] = x[(row0 + r) * Cz + k0 + k];
        }
        // stage W tile [32 x 64]
        for (int idx = tid; idx < PT_K * Hz; idx += 256) {
            int k = idx / Hz, n = idx % Hz;
            ws[k][n] = W[(long)(k0 + k) * Hz + n];
        }
        __syncthreads();

        #pragma unroll
        for (int k = 0; k < PT_K; k++) {
            float a[4], b[4];
            #pragma unroll
            for (int i = 0; i < 4; i++) a[i] = xs[tr * 4 + i][k];
            #pragma unroll
            for (int j = 0; j < 4; j++) b[j] = ws[k][tc * 4 + j];
            #pragma unroll
            for (int i = 0; i < 4; i++)
                #pragma unroll
                for (int j = 0; j < 4; j++)
                    acc[i][j] += a[i] * b[j];
        }
        __syncthreads();
    }

    #pragma unroll
    for (int i = 0; i < 4; i++)
        #pragma unroll
        for (int j = 0; j < 4; j++)
            out[(row0 + tr * 4 + i) * Hz + tc * 4 + j] = acc[i][j];
}

// ---------------------------------------------------------------------------
// Flash attention, causal, online softmax.
// grid = (T/64, B). block = 256 threads. 64 query rows per block.
// Thread owns 4 rows x 4 cols of S (and 4 rows x 4 H-cols of O).
// Row reductions via shfl across the 16 lanes of a row group.
// ---------------------------------------------------------------------------
#define AT 64
#define SPAD 65
#define ASMEM (4 * AT * SPAD * 4)   // Qs, Ks, Vs, Ps  (66560 bytes)

__global__ void attn_kernel(float* __restrict__ out) {
    extern __shared__ float sm[];
    float* Qs = sm;                  // [64][65], pre-scaled by C^-0.5
    float* Ks = Qs + AT * SPAD;      // [64][65]
    float* Vs = Ks + AT * SPAD;      // [64][65]
    float* Ps = Vs + AT * SPAD;      // [64][65]

    const float scale = 0.03608439182435161f;  // 768^-0.5

    int b  = blockIdx.y;
    int qi = blockIdx.x;
    int tid = threadIdx.x;
    int tr = tid / 16;  // row group
    int tc = tid % 16;  // col group

    const float* qg = g_q + (long)b * Tz * Hz;
    const float* kg = g_k + (long)b * Tz * Hz;
    const float* vg = g_v + (long)b * Tz * Hz;

    // stage Q tile (pre-scaled)
    for (int idx = tid; idx < AT * Hz; idx += 256) {
        int r = idx / Hz, h = idx % Hz;
        Qs[r * SPAD + h] = qg[(qi * AT + r) * Hz + h] * scale;
    }

    float o[4][4] = {};
    float m[4], l[4];
    #pragma unroll
    for (int i = 0; i < 4; i++) { m[i] = -INFINITY; l[i] = 0.0f; }

    for (int j = 0; j <= qi; j++) {
        __syncthreads();   // protect Ks/Vs/Ps from previous iteration readers
        // stage K,V tiles
        for (int idx = tid; idx < AT * Hz; idx += 256) {
            int r = idx / Hz, h = idx % Hz;
            Ks[r * SPAD + h] = kg[(j * AT + r) * Hz + h];
            Vs[r * SPAD + h] = vg[(j * AT + r) * Hz + h];
        }
        __syncthreads();

        // S = Q K^T  (4x4 per thread)
        float s[4][4] = {};
        #pragma unroll 8
        for (int h = 0; h < Hz; h++) {
            float a[4], bb[4];
            #pragma unroll
            for (int i = 0; i < 4; i++) a[i] = Qs[(tr * 4 + i) * SPAD + h];
            #pragma unroll
            for (int jj = 0; jj < 4; jj++) bb[jj] = Ks[(tc * 4 + jj) * SPAD + h];
            #pragma unroll
            for (int i = 0; i < 4; i++)
                #pragma unroll
                for (int jj = 0; jj < 4; jj++)
                    s[i][jj] += a[i] * bb[jj];
        }

        // causal mask on the diagonal tile
        if (j == qi) {
            #pragma unroll
            for (int i = 0; i < 4; i++)
                #pragma unroll
                for (int jj = 0; jj < 4; jj++)
                    if (tc * 4 + jj > tr * 4 + i) s[i][jj] = -INFINITY;
        }

        // online softmax update
        float mt[4], rs[4], alpha[4];
        #pragma unroll
        for (int i = 0; i < 4; i++) {
            mt[i] = s[i][0];
            #pragma unroll
            for (int jj = 1; jj < 4; jj++) mt[i] = fmaxf(mt[i], s[i][jj]);
        }
        #pragma unroll
        for (int off = 1; off < 16; off <<= 1) {
            #pragma unroll
            for (int i = 0; i < 4; i++)
                mt[i] = fmaxf(mt[i], __shfl_xor_sync(0xffffffffu, mt[i], off));
        }
        #pragma unroll
        for (int i = 0; i < 4; i++) {
            float mn = fmaxf(m[i], mt[i]);
            alpha[i] = __expf(m[i] - mn);
            m[i] = mn;
            float r = 0.0f;
            #pragma unroll
            for (int jj = 0; jj < 4; jj++) {
                s[i][jj] = __expf(s[i][jj] - mn);
                r += s[i][jj];
            }
            rs[i] = r;
        }
        #pragma unroll
        for (int off = 1; off < 16; off <<= 1) {
            #pragma unroll
            for (int i = 0; i < 4; i++)
                rs[i] += __shfl_xor_sync(0xffffffffu, rs[i], off);
        }
        #pragma unroll
        for (int i = 0; i < 4; i++) {
            l[i] = l[i] * alpha[i] + rs[i];
            #pragma unroll
            for (int jj = 0; jj < 4; jj++) o[i][jj] *= alpha[i];
        }

        // stage P
        #pragma unroll
        for (int i = 0; i < 4; i++)
            #pragma unroll
            for (int jj = 0; jj < 4; jj++)
                Ps[(tr * 4 + i) * SPAD + tc * 4 + jj] = s[i][jj];
        __syncthreads();

        // O += P V   (thread owns rows tr*4.., H-cols tc*4..)
        #pragma unroll 8
        for (int c = 0; c < AT; c++) {
            float pa[4], vb[4];
            #pragma unroll
            for (int i = 0; i < 4; i++) pa[i] = Ps[(tr * 4 + i) * SPAD + c];
            #pragma unroll
            for (int jj = 0; jj < 4; jj++) vb[jj] = Vs[c * SPAD + tc * 4 + jj];
            #pragma unroll
            for (int i = 0; i < 4; i++)
                #pragma unroll
                for (int jj = 0; jj < 4; jj++)
                    o[i][jj] += pa[i] * vb[jj];
        }
    }

    // normalize + write
    #pragma unroll
    for (int i = 0; i < 4; i++) {
        float inv = 1.0f / l[i];
        #pragma unroll
        for (int jj = 0; jj < 4; jj++)
            out[((long)b * Tz + qi * AT + tr * 4 + i) * Hz + tc * 4 + jj] =
                o[i][jj] * inv;
    }
}

extern "C" void kernel_launch(void* const* d_in, const int* in_sizes, int n_in,
                              void* d_out, int out_size) {
    const float* x  = (const float*)d_in[0];
    const float* Wk = (const float*)d_in[1];
    const float* Wq = (const float*)d_in[2];
    const float* Wv = (const float*)d_in[3];
    float* out = (float*)d_out;

    dim3 pg((Bz * Tz) / PT_M, 3);
    proj_kernel<<<pg, 256>>>(x, Wk, Wq, Wv);

    cudaFuncSetAttribute(attn_kernel,
                         cudaFuncAttributeMaxDynamicSharedMemorySize, ASMEM);
    dim3 ag(Tz / AT, Bz);
    attn_kernel<<<ag, 256, ASMEM>>>(out);
}

// round 3
// speedup vs baseline: 1.2122x; 1.2122x over previous
#include <cuda_runtime.h>
#include <math.h>

#define Bz 8
#define Tz 4096
#define Cz 768
#define Hz 64

// q/k/v scratch (allocation-free rule: __device__ globals)
__device__ float g_q[Bz * Tz * Hz];
__device__ float g_k[Bz * Tz * Hz];
__device__ float g_v[Bz * Tz * Hz];

// ---------------------------------------------------------------------------
// Projection: out[b,t,h] = sum_c x[b,t,c] * W[c,h]
// M = B*T = 32768, K = 768, N = 64. grid = (256, 3). 128x64 tile, 256 thr,
// 8x4 register blocking, all smem reads vectorized (LDS.128, conflict-free).
// ---------------------------------------------------------------------------
#define PM 128
#define PK 32

__global__ void proj_kernel(const float* __restrict__ x,
                            const float* __restrict__ Wk,
                            const float* __restrict__ Wq,
                            const float* __restrict__ Wv) {
    __shared__ float xsT[PK][PM + 4];  // [k][r]  (transposed x tile)
    __shared__ float ws[PK][Hz + 4];   // [k][n]

    int mat = blockIdx.y;
    const float* W = (mat == 0) ? Wq : ((mat == 1) ? Wk : Wv);
    float* out = (mat == 0) ? g_q : ((mat == 1) ? g_k : g_v);

    long row0 = (long)blockIdx.x * PM;
    int tid = threadIdx.x;
    int tr = tid / 16;   // 0..15 -> rows tr*8 .. tr*8+7
    int tc = tid % 16;   // 0..15 -> cols tc*4 .. tc*4+3

    float acc[8][4] = {};

    for (int k0 = 0; k0 < Cz; k0 += PK) {
        // stage x tile transposed: read coalesced, write [k][r]
        for (int idx = tid; idx < PM * PK; idx += 256) {
            int r = idx / PK, k = idx % PK;
            xsT[k][r] = x[(row0 + r) * Cz + k0 + k];
        }
        // stage W tile [32 x 64]
        for (int idx = tid; idx < PK * Hz; idx += 256) {
            int k = idx / Hz, n = idx % Hz;
            ws[k][n] = W[(long)(k0 + k) * Hz + n];
        }
        __syncthreads();

        #pragma unroll 8
        for (int k = 0; k < PK; k++) {
            float4 b  = *(const float4*)&ws[k][tc * 4];
            float4 a0 = *(const float4*)&xsT[k][tr * 8];
            float4 a1 = *(const float4*)&xsT[k][tr * 8 + 4];
            float av[8] = {a0.x, a0.y, a0.z, a0.w, a1.x, a1.y, a1.z, a1.w};
            #pragma unroll
            for (int i = 0; i < 8; i++) {
                acc[i][0] += av[i] * b.x;
                acc[i][1] += av[i] * b.y;
                acc[i][2] += av[i] * b.z;
                acc[i][3] += av[i] * b.w;
            }
        }
        __syncthreads();
    }

    #pragma unroll
    for (int i = 0; i < 8; i++) {
        float4 r4 = make_float4(acc[i][0], acc[i][1], acc[i][2], acc[i][3]);
        *(float4*)&out[(row0 + tr * 8 + i) * Hz + tc * 4] = r4;
    }
}

// ---------------------------------------------------------------------------
// Flash attention, causal, online softmax, fully vectorized smem access.
// grid = (32, B): block bx handles q-tiles {bx, 63-bx} (65 steps each ->
// perfectly balanced causal schedule in one wave).
// Layouts: Qt[h][r], Kt[h][c] (h-major), Pt[c][r] (transposed P), Vs[c][h].
// Every compute-loop operand is a conflict-free LDS.128.
// ---------------------------------------------------------------------------
#define AT 64
#define NQ (Tz / AT)
#define LDW (AT + 4)                  // 68 floats, 16B-aligned rows
#define ASMEM (4 * AT * LDW * 4)      // Qt, Kt, Vs, Pt = 69632 bytes

__global__ void attn_kernel(float* __restrict__ out) {
    extern __shared__ float sm[];
    float* Qt = sm;                   // [64][68]  Qt[h][r], pre-scaled
    float* Kt = Qt + AT * LDW;        // [64][68]  Kt[h][c]
    float* Vs = Kt + AT * LDW;        // [64][68]  Vs[c][h]
    float* Pt = Vs + AT * LDW;        // [64][68]  Pt[c][r]

    const float scale = 0.03608439182435161f;  // 768^-0.5

    int b   = blockIdx.y;
    int tid = threadIdx.x;
    int tr  = tid / 16;  // row group: rows tr*4..tr*4+3
    int tc  = tid % 16;  // col group: cols tc*4..tc*4+3

    const float* qg = g_q + (long)b * Tz * Hz;
    const float* kg = g_k + (long)b * Tz * Hz;
    const float* vg = g_v + (long)b * Tz * Hz;

    for (int which = 0; which < 2; which++) {
        int qi = (which == 0) ? blockIdx.x : (NQ - 1 - blockIdx.x);

        __syncthreads();  // protect Qt from previous q-tile readers
        // stage Q transposed + pre-scaled
        for (int idx = tid; idx < AT * Hz; idx += 256) {
            int r = idx / Hz, h = idx % Hz;
            Qt[h * LDW + r] = qg[((long)qi * AT + r) * Hz + h] * scale;
        }

        float o[4][4] = {};
        float m[4], l[4];
        #pragma unroll
        for (int i = 0; i < 4; i++) { m[i] = -INFINITY; l[i] = 0.0f; }

        for (int j = 0; j <= qi; j++) {
            __syncthreads();  // prev iteration done reading Kt/Vs/Pt
            for (int idx = tid; idx < AT * Hz; idx += 256) {
                int r = idx / Hz, h = idx % Hz;
                Kt[h * LDW + r] = kg[((long)j * AT + r) * Hz + h];
                Vs[r * LDW + h] = vg[((long)j * AT + r) * Hz + h];
            }
            __syncthreads();

            // S = Q K^T : per h, 2x LDS.128 -> 16 FMA
            float s[4][4] = {};
            #pragma unroll 8
            for (int h = 0; h < Hz; h++) {
                float4 a  = *(const float4*)&Qt[h * LDW + tr * 4];
                float4 bb = *(const float4*)&Kt[h * LDW + tc * 4];
                float av[4] = {a.x, a.y, a.z, a.w};
                #pragma unroll
                for (int i = 0; i < 4; i++) {
                    s[i][0] += av[i] * bb.x;
                    s[i][1] += av[i] * bb.y;
                    s[i][2] += av[i] * bb.z;
                    s[i][3] += av[i] * bb.w;
                }
            }

            // causal mask on the diagonal tile
            if (j == qi) {
                #pragma unroll
                for (int i = 0; i < 4; i++)
                    #pragma unroll
                    for (int jj = 0; jj < 4; jj++)
                        if (tc * 4 + jj > tr * 4 + i) s[i][jj] = -INFINITY;
            }

            // online softmax update (row reductions across 16 lanes)
            float mt[4], rs[4], alpha[4];
            #pragma unroll
            for (int i = 0; i < 4; i++) {
                mt[i] = fmaxf(fmaxf(s[i][0], s[i][1]), fmaxf(s[i][2], s[i][3]));
            }
            #pragma unroll
            for (int off = 1; off < 16; off <<= 1) {
                #pragma unroll
                for (int i = 0; i < 4; i++)
                    mt[i] = fmaxf(mt[i], __shfl_xor_sync(0xffffffffu, mt[i], off));
            }
            #pragma unroll
            for (int i = 0; i < 4; i++) {
                float mn = fmaxf(m[i], mt[i]);
                alpha[i] = __expf(m[i] - mn);
                m[i] = mn;
                float r = 0.0f;
                #pragma unroll
                for (int jj = 0; jj < 4; jj++) {
                    s[i][jj] = __expf(s[i][jj] - mn);
                    r += s[i][jj];
                }
                rs[i] = r;
            }
            #pragma unroll
            for (int off = 1; off < 16; off <<= 1) {
                #pragma unroll
                for (int i = 0; i < 4; i++)
                    rs[i] += __shfl_xor_sync(0xffffffffu, rs[i], off);
            }
            #pragma unroll
            for (int i = 0; i < 4; i++) {
                l[i] = l[i] * alpha[i] + rs[i];
                #pragma unroll
                for (int jj = 0; jj < 4; jj++) o[i][jj] *= alpha[i];
            }

            // stage P transposed: Pt[c][r], one STS.128 per owned column
            #pragma unroll
            for (int jj = 0; jj < 4; jj++) {
                float4 p4 = make_float4(s[0][jj], s[1][jj], s[2][jj], s[3][jj]);
                *(float4*)&Pt[(tc * 4 + jj) * LDW + tr * 4] = p4;
            }
            __syncthreads();

            // O += P V : per c, 2x LDS.128 -> 16 FMA
            #pragma unroll 8
            for (int c = 0; c < AT; c++) {
                float4 pa = *(const float4*)&Pt[c * LDW + tr * 4];
                float4 vb = *(const float4*)&Vs[c * LDW + tc * 4];
                float pv[4] = {pa.x, pa.y, pa.z, pa.w};
                #pragma unroll
                for (int i = 0; i < 4; i++) {
                    o[i][0] += pv[i] * vb.x;
                    o[i][1] += pv[i] * vb.y;
                    o[i][2] += pv[i] * vb.z;
                    o[i][3] += pv[i] * vb.w;
                }
            }
        }

        // normalize + write (vectorized)
        #pragma unroll
        for (int i = 0; i < 4; i++) {
            float inv = 1.0f / l[i];
            float4 r4 = make_float4(o[i][0] * inv, o[i][1] * inv,
                                    o[i][2] * inv, o[i][3] * inv);
            *(float4*)&out[((long)b * Tz + (long)qi * AT + tr * 4 + i) * Hz + tc * 4] = r4;
        }
    }
}

extern "C" void kernel_launch(void* const* d_in, const int* in_sizes, int n_in,
                              void* d_out, int out_size) {
    const float* x  = (const float*)d_in[0];
    const float* Wk = (const float*)d_in[1];
    const float* Wq = (const float*)d_in[2];
    const float* Wv = (const float*)d_in[3];
    float* out = (float*)d_out;

    dim3 pg((Bz * Tz) / PM, 3);
    proj_kernel<<<pg, 256>>>(x, Wk, Wq, Wv);

    cudaFuncSetAttribute(attn_kernel,
                         cudaFuncAttributeMaxDynamicSharedMemorySize, ASMEM);
    dim3 ag(NQ / 2, Bz);
    attn_kernel<<<ag, 256, ASMEM>>>(out);
}

// round 6
// speedup vs baseline: 1.7199x; 1.4189x over previous
#include <cuda_runtime.h>
#include <cuda_bf16.h>
#include <cstdint>
#include <stdint.h>
#include <math.h>

#define Bz 8
#define Tz 4096
#define Cz 768
#define Hz 64

// global scratch (allocation-free rule)
__device__ __nv_bfloat16 g_qh[Bz * Tz * Hz];
__device__ __nv_bfloat16 g_ql[Bz * Tz * Hz];
__device__ __nv_bfloat16 g_kh[Bz * Tz * Hz];
__device__ __nv_bfloat16 g_kl[Bz * Tz * Hz];
__device__ __nv_bfloat16 g_vh[Bz * Tz * Hz];
__device__ __nv_bfloat16 g_vl[Bz * Tz * Hz];
__device__ __nv_bfloat16 g_wth[3 * Hz * Cz];   // W^T hi  [mat][h][c]
__device__ __nv_bfloat16 g_wtl[3 * Hz * Cz];   // W^T lo

// ---------------------------------------------------------------------------
// helpers
// ---------------------------------------------------------------------------
__device__ __forceinline__ uint32_t smem_u32(const void* p) {
    uint32_t a;
    asm("{ .reg .u64 t; cvta.to.shared.u64 t, %1; cvt.u32.u64 %0, t; }"
        : "=r"(a) : "l"(p));
    return a;
}

__device__ __forceinline__ void ldsm4(uint32_t* r, uint32_t a) {
    asm volatile("ldmatrix.sync.aligned.m8n8.x4.shared.b16 {%0,%1,%2,%3}, [%4];"
        : "=r"(r[0]), "=r"(r[1]), "=r"(r[2]), "=r"(r[3]) : "r"(a));
}
__device__ __forceinline__ void ldsm2(uint32_t* r, uint32_t a) {
    asm volatile("ldmatrix.sync.aligned.m8n8.x2.shared.b16 {%0,%1}, [%2];"
        : "=r"(r[0]), "=r"(r[1]) : "r"(a));
}
__device__ __forceinline__ void ldsm2t(uint32_t* r, uint32_t a) {
    asm volatile("ldmatrix.sync.aligned.m8n8.x2.trans.shared.b16 {%0,%1}, [%2];"
        : "=r"(r[0]), "=r"(r[1]) : "r"(a));
}
__device__ __forceinline__ void mma16816(float* d, const uint32_t* a,
                                         const uint32_t* b) {
    asm volatile(
        "mma.sync.aligned.m16n8k16.row.col.f32.bf16.bf16.f32 "
        "{%0,%1,%2,%3}, {%4,%5,%6,%7}, {%8,%9}, {%0,%1,%2,%3};"
        : "+f"(d[0]), "+f"(d[1]), "+f"(d[2]), "+f"(d[3])
        : "r"(a[0]), "r"(a[1]), "r"(a[2]), "r"(a[3]), "r"(b[0]), "r"(b[1]));
}

// split two floats into packed bf16x2 hi + lo residual
__device__ __forceinline__ void split2(float f0, float f1,
                                       uint32_t& hi, uint32_t& lo) {
    __nv_bfloat162 h = __floats2bfloat162_rn(f0, f1);
    float g0 = __low2float(h), g1 = __high2float(h);
    __nv_bfloat162 l = __floats2bfloat162_rn(f0 - g0, f1 - g1);
    hi = reinterpret_cast<uint32_t&>(h);
    lo = reinterpret_cast<uint32_t&>(l);
}
__device__ __forceinline__ void splits(float v, __nv_bfloat16& hi,
                                       __nv_bfloat16& lo) {
    hi = __float2bfloat16(v);
    lo = __float2bfloat16(v - __bfloat162float(hi));
}

// ---------------------------------------------------------------------------
// prep: W -> W^T bf16 hi/lo   grid(3), 256 thr
// ---------------------------------------------------------------------------
__global__ void prep_kernel(const float* __restrict__ Wk,
                            const float* __restrict__ Wq,
                            const float* __restrict__ Wv) {
    int mat = blockIdx.x;
    const float* W = (mat == 0) ? Wq : ((mat == 1) ? Wk : Wv);
    for (int i = threadIdx.x; i < Cz * Hz; i += 256) {
        int c = i / Hz, h = i % Hz;
        __nv_bfloat16 hi, lo;
        splits(W[i], hi, lo);
        g_wth[mat * Hz * Cz + h * Cz + c] = hi;
        g_wtl[mat * Hz * Cz + h * Cz + c] = lo;
    }
}

// ---------------------------------------------------------------------------
// projection: q/k/v = x @ W, written as bf16 hi/lo (q pre-scaled)
// grid (256, 3), 256 threads, 8 warps x 16 rows, k-chunks of 64
// ---------------------------------------------------------------------------
#define PLD 72
#define PXH 0
#define PXL 18432
#define PWH 36864
#define PWL 46080
#define PSMEM 55296

__global__ void __launch_bounds__(256) proj_kernel(const float* __restrict__ x) {
    extern __shared__ char smem[];
    uint32_t sb = smem_u32(smem);

    int mat = blockIdx.y;
    __nv_bfloat16* outh = (mat == 0) ? g_qh : ((mat == 1) ? g_kh : g_vh);
    __nv_bfloat16* outl = (mat == 0) ? g_ql : ((mat == 1) ? g_kl : g_vl);
    const __nv_bfloat16* wth = g_wth + mat * Hz * Cz;
    const __nv_bfloat16* wtl = g_wtl + mat * Hz * Cz;

    long row0 = (long)blockIdx.x * 128;
    int tid = threadIdx.x, wid = tid / 32, lane = tid % 32;
    int wr0 = wid * 16;
    int rr = lane % 8, grp = lane / 8;

    float acc[8][4] = {};

    for (int it = 0; it < 12; it++) {
        int k0 = it * 64;
        __syncthreads();
        // stage x (convert fp32 -> bf16 hi/lo)
        for (int i = tid; i < 128 * 16; i += 256) {
            int r = i / 16, c4 = (i % 16) * 4;
            float4 xv = *(const float4*)&x[(row0 + r) * Cz + k0 + c4];
            uint32_t h0, l0, h1, l1;
            split2(xv.x, xv.y, h0, l0);
            split2(xv.z, xv.w, h1, l1);
            uint32_t off = (uint32_t)(r * PLD + c4) * 2;
            *(uint2*)(smem + PXH + off) = make_uint2(h0, h1);
            *(uint2*)(smem + PXL + off) = make_uint2(l0, l1);
        }
        // stage W^T (already bf16)
        for (int i = tid; i < 64 * 8; i += 256) {
            int h = i / 8, ch = i % 8;
            uint32_t off = (uint32_t)(h * PLD + ch * 8) * 2;
            *(uint4*)(smem + PWH + off) = *(const uint4*)(wth + h * Cz + k0 + ch * 8);
            *(uint4*)(smem + PWL + off) = *(const uint4*)(wtl + h * Cz + k0 + ch * 8);
        }
        __syncthreads();

        #pragma unroll
        for (int kc = 0; kc < 4; kc++) {
            uint32_t ah[4], al[4];
            uint32_t aoff = (uint32_t)((wr0 + rr + (grp & 1) * 8) * PLD
                                       + kc * 16 + (grp >> 1) * 8) * 2;
            ldsm4(ah, sb + PXH + aoff);
            ldsm4(al, sb + PXL + aoff);
            #pragma unroll
            for (int n = 0; n < 8; n++) {
                uint32_t bh[2], bl[2];
                uint32_t boff = (uint32_t)((n * 8 + rr) * PLD
                                           + kc * 16 + (grp & 1) * 8) * 2;
                ldsm2(bh, sb + PWH + boff);
                ldsm2(bl, sb + PWL + boff);
                mma16816(acc[n], ah, bh);
                mma16816(acc[n], ah, bl);
                mma16816(acc[n], al, bh);
            }
        }
    }

    float scale = (mat == 0) ? 0.03608439182435161f : 1.0f;
    long rA = row0 + wr0 + lane / 4;
    long rB = rA + 8;
    int cb = 2 * (lane % 4);
    #pragma unroll
    for (int n = 0; n < 8; n++) {
        uint32_t hi, lo;
        split2(acc[n][0] * scale, acc[n][1] * scale, hi, lo);
        *(uint32_t*)&outh[rA * Hz + n * 8 + cb] = hi;
        *(uint32_t*)&outl[rA * Hz + n * 8 + cb] = lo;
        split2(acc[n][2] * scale, acc[n][3] * scale, hi, lo);
        *(uint32_t*)&outh[rB * Hz + n * 8 + cb] = hi;
        *(uint32_t*)&outl[rB * Hz + n * 8 + cb] = lo;
    }
}

// ---------------------------------------------------------------------------
// flash attention on mma.sync: q-tile 128 (warp = 16 rows), k-tile 64
// grid (32, 8); longest q-tiles first
// ---------------------------------------------------------------------------
#define LDA 72
#define AQH 0
#define AQL 18432
#define AKV 36864          // K hi, K lo, V hi, V lo: 4 x 9216
#define ASMEM 73728

__global__ void __launch_bounds__(256) attn_kernel(float* __restrict__ out) {
    extern __shared__ char smem[];
    uint32_t sb = smem_u32(smem);

    int tid = threadIdx.x, wid = tid / 32, lane = tid % 32;
    int b = blockIdx.y;
    int qt = (int)(gridDim.x - 1 - blockIdx.x);
    int q0 = qt * 128;
    int rr = lane % 8, grp = lane / 8;
    int wr0 = wid * 16;
    int r0a = q0 + wr0;

    // stage Q hi/lo
    const __nv_bfloat16* gqh = g_qh + ((long)b * Tz + q0) * Hz;
    const __nv_bfloat16* gql = g_ql + ((long)b * Tz + q0) * Hz;
    for (int i = tid; i < 2048; i += 256) {
        int arr = i / 1024, idx = i % 1024;
        int r = idx / 8, ch = idx % 8;
        const __nv_bfloat16* src = arr ? gql : gqh;
        *(uint4*)(smem + (arr ? AQL : AQH) + (uint32_t)(r * LDA + ch * 8) * 2) =
            *(const uint4*)(src + r * Hz + ch * 8);
    }
    __syncthreads();

    // Q fragments (held for the whole tile)
    uint32_t qh[4][4], ql[4][4];
    #pragma unroll
    for (int kc = 0; kc < 4; kc++) {
        uint32_t aoff = (uint32_t)((wr0 + rr + (grp & 1) * 8) * LDA
                                   + kc * 16 + (grp >> 1) * 8) * 2;
        ldsm4(qh[kc], sb + AQH + aoff);
        ldsm4(ql[kc], sb + AQL + aoff);
    }

    float O[8][4] = {};
    float mrow[2] = {-1e30f, -1e30f};
    float lrow[2] = {0.0f, 0.0f};

    const __nv_bfloat16* gk[2] = {g_kh + (long)b * Tz * Hz, g_kl + (long)b * Tz * Hz};
    const __nv_bfloat16* gv[2] = {g_vh + (long)b * Tz * Hz, g_vl + (long)b * Tz * Hz};

    int njt = 2 * qt + 2;
    for (int j = 0; j < njt; j++) {
        int jb = j * 64;
        __syncthreads();
        // stage K hi/lo, V hi/lo
        for (int i = tid; i < 2048; i += 256) {
            int arr = i / 512, idx = i % 512;
            int r = idx / 8, ch = idx % 8;
            const __nv_bfloat16* src =
                (arr == 0) ? gk[0] : (arr == 1) ? gk[1] : (arr == 2) ? gv[0] : gv[1];
            *(uint4*)(smem + AKV + arr * 9216 + (uint32_t)(r * LDA + ch * 8) * 2) =
                *(const uint4*)(src + (long)(jb + r) * Hz + ch * 8);
        }
        __syncthreads();

        if (jb > r0a + 15) continue;   // fully masked for this warp

        // ---- S = Q K^T ----
        float S[8][4] = {};
        #pragma unroll
        for (int n = 0; n < 8; n++) {
            #pragma unroll
            for (int kc = 0; kc < 4; kc++) {
                uint32_t bh[2], bl[2];
                uint32_t boff = (uint32_t)((n * 8 + rr) * LDA
                                           + kc * 16 + (grp & 1) * 8) * 2;
                ldsm2(bh, sb + AKV + 0 * 9216 + boff);
                ldsm2(bl, sb + AKV + 1 * 9216 + boff);
                mma16816(S[n], qh[kc], bh);
                mma16816(S[n], qh[kc], bl);
                mma16816(S[n], ql[kc], bh);
            }
        }

        // ---- causal mask ----
        int rA = r0a + lane / 4;
        int rB = rA + 8;
        if (jb + 63 > r0a) {
            #pragma unroll
            for (int n = 0; n < 8; n++) {
                int c0 = jb + n * 8 + 2 * (lane % 4);
                if (c0 > rA)     S[n][0] = -1e30f;
                if (c0 + 1 > rA) S[n][1] = -1e30f;
                if (c0 > rB)     S[n][2] = -1e30f;
                if (c0 + 1 > rB) S[n][3] = -1e30f;
            }
        }

        // ---- online softmax (rows rA, rB; quad reduction) ----
        float mA = -1e30f, mB = -1e30f;
        #pragma unroll
        for (int n = 0; n < 8; n++) {
            mA = fmaxf(mA, fmaxf(S[n][0], S[n][1]));
            mB = fmaxf(mB, fmaxf(S[n][2], S[n][3]));
        }
        #pragma unroll
        for (int off = 1; off < 4; off <<= 1) {
            mA = fmaxf(mA, __shfl_xor_sync(0xffffffffu, mA, off));
            mB = fmaxf(mB, __shfl_xor_sync(0xffffffffu, mB, off));
        }
        float mnA = fmaxf(mrow[0], mA), mnB = fmaxf(mrow[1], mB);
        float aA = __expf(mrow[0] - mnA), aB = __expf(mrow[1] - mnB);
        mrow[0] = mnA; mrow[1] = mnB;
        float sA = 0.0f, sB = 0.0f;
        #pragma unroll
        for (int n = 0; n < 8; n++) {
            S[n][0] = __expf(S[n][0] - mnA); sA += S[n][0];
            S[n][1] = __expf(S[n][1] - mnA); sA += S[n][1];
            S[n][2] = __expf(S[n][2] - mnB); sB += S[n][2];
            S[n][3] = __expf(S[n][3] - mnB); sB += S[n][3];
        }
        #pragma unroll
        for (int off = 1; off < 4; off <<= 1) {
            sA += __shfl_xor_sync(0xffffffffu, sA, off);
            sB += __shfl_xor_sync(0xffffffffu, sB, off);
        }
        lrow[0] = lrow[0] * aA + sA;
        lrow[1] = lrow[1] * aB + sB;
        #pragma unroll
        for (int n = 0; n < 8; n++) {
            O[n][0] *= aA; O[n][1] *= aA; O[n][2] *= aB; O[n][3] *= aB;
        }

        // ---- O += P V (P from registers) ----
        #pragma unroll
        for (int kc = 0; kc < 4; kc++) {
            int t0 = 2 * kc, t1 = 2 * kc + 1;
            uint32_t ph[4], pl[4];
            split2(S[t0][0], S[t0][1], ph[0], pl[0]);
            split2(S[t0][2], S[t0][3], ph[1], pl[1]);
            split2(S[t1][0], S[t1][1], ph[2], pl[2]);
            split2(S[t1][2], S[t1][3], ph[3], pl[3]);
            #pragma unroll
            for (int n = 0; n < 8; n++) {
                uint32_t vh[2], vl[2];
                uint32_t voff = (uint32_t)((kc * 16 + (grp & 1) * 8 + rr) * LDA
                                           + n * 8) * 2;
                ldsm2t(vh, sb + AKV + 2 * 9216 + voff);
                ldsm2t(vl, sb + AKV + 3 * 9216 + voff);
                mma16816(O[n], ph, vh);
                mma16816(O[n], ph, vl);
                mma16816(O[n], pl, vh);
            }
        }
    }

    // epilogue
    float invA = 1.0f / lrow[0];
    float invB = 1.0f / lrow[1];
    long rA = (long)b * Tz + r0a + lane / 4;
    long rB = rA + 8;
    int cb = 2 * (lane % 4);
    #pragma unroll
    for (int n = 0; n < 8; n++) {
        *(float2*)&out[rA * Hz + n * 8 + cb] =
            make_float2(O[n][0] * invA, O[n][1] * invA);
        *(float2*)&out[rB * Hz + n * 8 + cb] =
            make_float2(O[n][2] * invB, O[n][3] * invB);
    }
}

extern "C" void kernel_launch(void* const* d_in, const int* in_sizes, int n_in,
                              void* d_out, int out_size) {
    const float* x  = (const float*)d_in[0];
    const float* Wk = (const float*)d_in[1];
    const float* Wq = (const float*)d_in[2];
    const float* Wv = (const float*)d_in[3];
    float* out = (float*)d_out;

    prep_kernel<<<3, 256>>>(Wk, Wq, Wv);

    cudaFuncSetAttribute(proj_kernel,
                         cudaFuncAttributeMaxDynamicSharedMemorySize, PSMEM);
    dim3 pg((Bz * Tz) / 128, 3);
    proj_kernel<<<pg, 256, PSMEM>>>(x);

    cudaFuncSetAttribute(attn_kernel,
                         cudaFuncAttributeMaxDynamicSharedMemorySize, ASMEM);
    dim3 ag(Tz / 128, Bz);
    attn_kernel<<<ag, 256, ASMEM>>>(out);
}

// round 7
// speedup vs baseline: 2.8164x; 1.6375x over previous
#include <cuda_runtime.h>
#include <cuda_bf16.h>
#include <cstdint>
#include <stdint.h>
#include <math.h>

#define Bz 8
#define Tz 4096
#define Cz 768
#define Hz 64

// global scratch (allocation-free rule)
__device__ __nv_bfloat16 g_qh[Bz * Tz * Hz];
__device__ __nv_bfloat16 g_ql[Bz * Tz * Hz];
__device__ __nv_bfloat16 g_kh[Bz * Tz * Hz];
__device__ __nv_bfloat16 g_kl[Bz * Tz * Hz];
__device__ __nv_bfloat16 g_vh[Bz * Tz * Hz];
__device__ __nv_bfloat16 g_vl[Bz * Tz * Hz];
__device__ __nv_bfloat16 g_wth[3 * Hz * Cz];   // W^T hi  [mat][h][c]
__device__ __nv_bfloat16 g_wtl[3 * Hz * Cz];   // W^T lo

// ---------------------------------------------------------------------------
// helpers
// ---------------------------------------------------------------------------
__device__ __forceinline__ uint32_t smem_u32(const void* p) {
    uint32_t a;
    asm("{ .reg .u64 t; cvta.to.shared.u64 t, %1; cvt.u32.u64 %0, t; }"
        : "=r"(a) : "l"(p));
    return a;
}
__device__ __forceinline__ void ldsm4(uint32_t* r, uint32_t a) {
    asm volatile("ldmatrix.sync.aligned.m8n8.x4.shared.b16 {%0,%1,%2,%3}, [%4];"
        : "=r"(r[0]), "=r"(r[1]), "=r"(r[2]), "=r"(r[3]) : "r"(a));
}
__device__ __forceinline__ void ldsm4t(uint32_t* r, uint32_t a) {
    asm volatile("ldmatrix.sync.aligned.m8n8.x4.trans.shared.b16 {%0,%1,%2,%3}, [%4];"
        : "=r"(r[0]), "=r"(r[1]), "=r"(r[2]), "=r"(r[3]) : "r"(a));
}
__device__ __forceinline__ void ldsm2(uint32_t* r, uint32_t a) {
    asm volatile("ldmatrix.sync.aligned.m8n8.x2.shared.b16 {%0,%1}, [%2];"
        : "=r"(r[0]), "=r"(r[1]) : "r"(a));
}
__device__ __forceinline__ void mma16816(float* d, const uint32_t* a,
                                         const uint32_t* b) {
    asm volatile(
        "mma.sync.aligned.m16n8k16.row.col.f32.bf16.bf16.f32 "
        "{%0,%1,%2,%3}, {%4,%5,%6,%7}, {%8,%9}, {%0,%1,%2,%3};"
        : "+f"(d[0]), "+f"(d[1]), "+f"(d[2]), "+f"(d[3])
        : "r"(a[0]), "r"(a[1]), "r"(a[2]), "r"(a[3]), "r"(b[0]), "r"(b[1]));
}
__device__ __forceinline__ void cp16(uint32_t dst, const void* src) {
    asm volatile("cp.async.cg.shared.global [%0], [%1], 16;"
                 :: "r"(dst), "l"(src) : "memory");
}
__device__ __forceinline__ void cpcommit() {
    asm volatile("cp.async.commit_group;" ::: "memory");
}
template <int N> __device__ __forceinline__ void cpwait() {
    asm volatile("cp.async.wait_group %0;" :: "n"(N) : "memory");
}

// split two floats into packed bf16x2 hi + lo residual
__device__ __forceinline__ void split2(float f0, float f1,
                                       uint32_t& hi, uint32_t& lo) {
    __nv_bfloat162 h = __floats2bfloat162_rn(f0, f1);
    float g0 = __low2float(h), g1 = __high2float(h);
    __nv_bfloat162 l = __floats2bfloat162_rn(f0 - g0, f1 - g1);
    hi = reinterpret_cast<uint32_t&>(h);
    lo = reinterpret_cast<uint32_t&>(l);
}
__device__ __forceinline__ void splits(float v, __nv_bfloat16& hi,
                                       __nv_bfloat16& lo) {
    hi = __float2bfloat16(v);
    lo = __float2bfloat16(v - __bfloat162float(hi));
}

// ---------------------------------------------------------------------------
// prep: W -> W^T bf16 hi/lo   grid(48): mat = bx/16, slice = bx%16
// ---------------------------------------------------------------------------
__global__ void prep_kernel(const float* __restrict__ Wk,
                            const float* __restrict__ Wq,
                            const float* __restrict__ Wv) {
    int mat = blockIdx.x / 16;
    int slice = blockIdx.x % 16;
    const float* W = (mat == 0) ? Wq : ((mat == 1) ? Wk : Wv);
    int n = Cz * Hz / 16;                   // 3072 per slice
    int base = slice * n;
    for (int t = threadIdx.x; t < n; t += 256) {
        int i = base + t;
        int c = i / Hz, h = i % Hz;
        __nv_bfloat16 hi, lo;
        splits(W[i], hi, lo);
        g_wth[mat * Hz * Cz + h * Cz + c] = hi;
        g_wtl[mat * Hz * Cz + h * Cz + c] = lo;
    }
}

// ---------------------------------------------------------------------------
// projection: q/k/v = x @ W, written as bf16 hi/lo (q pre-scaled)
// grid (256, 3), 256 threads, 8 warps x 16 rows, k-chunks of 64
// ---------------------------------------------------------------------------
#define PLD 72
#define PXH 0
#define PXL 18432
#define PWH 36864
#define PWL 46080
#define PSMEM 55296

__global__ void __launch_bounds__(256) proj_kernel(const float* __restrict__ x) {
    extern __shared__ char smem[];
    uint32_t sb = smem_u32(smem);

    int mat = blockIdx.y;
    __nv_bfloat16* outh = (mat == 0) ? g_qh : ((mat == 1) ? g_kh : g_vh);
    __nv_bfloat16* outl = (mat == 0) ? g_ql : ((mat == 1) ? g_kl : g_vl);
    const __nv_bfloat16* wth = g_wth + mat * Hz * Cz;
    const __nv_bfloat16* wtl = g_wtl + mat * Hz * Cz;

    long row0 = (long)blockIdx.x * 128;
    int tid = threadIdx.x, wid = tid / 32, lane = tid % 32;
    int wr0 = wid * 16;
    int rr = lane % 8, grp = lane / 8;

    float acc[8][4] = {};

    for (int it = 0; it < 12; it++) {
        int k0 = it * 64;
        __syncthreads();
        for (int i = tid; i < 128 * 16; i += 256) {
            int r = i / 16, c4 = (i % 16) * 4;
            float4 xv = *(const float4*)&x[(row0 + r) * Cz + k0 + c4];
            uint32_t h0, l0, h1, l1;
            split2(xv.x, xv.y, h0, l0);
            split2(xv.z, xv.w, h1, l1);
            uint32_t off = (uint32_t)(r * PLD + c4) * 2;
            *(uint2*)(smem + PXH + off) = make_uint2(h0, h1);
            *(uint2*)(smem + PXL + off) = make_uint2(l0, l1);
        }
        for (int i = tid; i < 64 * 8; i += 256) {
            int h = i / 8, ch = i % 8;
            uint32_t off = (uint32_t)(h * PLD + ch * 8) * 2;
            *(uint4*)(smem + PWH + off) = *(const uint4*)(wth + h * Cz + k0 + ch * 8);
            *(uint4*)(smem + PWL + off) = *(const uint4*)(wtl + h * Cz + k0 + ch * 8);
        }
        __syncthreads();

        #pragma unroll
        for (int kc = 0; kc < 4; kc++) {
            uint32_t ah[4], al[4];
            uint32_t aoff = (uint32_t)((wr0 + rr + (grp & 1) * 8) * PLD
                                       + kc * 16 + (grp >> 1) * 8) * 2;
            ldsm4(ah, sb + PXH + aoff);
            ldsm4(al, sb + PXL + aoff);
            #pragma unroll
            for (int n = 0; n < 8; n++) {
                uint32_t bh[2], bl[2];
                uint32_t boff = (uint32_t)((n * 8 + rr) * PLD
                                           + kc * 16 + (grp & 1) * 8) * 2;
                ldsm2(bh, sb + PWH + boff);
                ldsm2(bl, sb + PWL + boff);
                mma16816(acc[n], ah, bh);
                mma16816(acc[n], ah, bl);
                mma16816(acc[n], al, bh);
            }
        }
    }

    float scale = (mat == 0) ? 0.03608439182435161f : 1.0f;
    long rA = row0 + wr0 + lane / 4;
    long rB = rA + 8;
    int cb = 2 * (lane % 4);
    #pragma unroll
    for (int n = 0; n < 8; n++) {
        uint32_t hi, lo;
        split2(acc[n][0] * scale, acc[n][1] * scale, hi, lo);
        *(uint32_t*)&outh[rA * Hz + n * 8 + cb] = hi;
        *(uint32_t*)&outl[rA * Hz + n * 8 + cb] = lo;
        split2(acc[n][2] * scale, acc[n][3] * scale, hi, lo);
        *(uint32_t*)&outh[rB * Hz + n * 8 + cb] = hi;
        *(uint32_t*)&outl[rB * Hz + n * 8 + cb] = lo;
    }
}

// ---------------------------------------------------------------------------
// flash attention: q-tile 128, k-tile 128 (2 x 64 halves), cp.async double buf
// grid (32, 8); longest q-tiles first
// ---------------------------------------------------------------------------
#define LDA 72
#define ARR 18432                       // one 128x72 half-array (bytes)
#define BUFS 73728                      // 4 arrays (Kh,Kl,Vh,Vl)
#define ASMEM (2 * BUFS)                // 147456

__global__ void __launch_bounds__(256) attn_kernel(float* __restrict__ out) {
    extern __shared__ char smem[];
    uint32_t sb = smem_u32(smem);

    int tid = threadIdx.x, wid = tid / 32, lane = tid % 32;
    int b = blockIdx.y;
    int qt = (int)(gridDim.x - 1 - blockIdx.x);
    int q0 = qt * 128;
    int rr = lane % 8, grp = lane / 8;
    int wr0 = wid * 16;
    int r0a = q0 + wr0;

    // ---- stage Q (into buf0 slots 0/1, reused afterwards) ----
    const __nv_bfloat16* gqh = g_qh + ((long)b * Tz + q0) * Hz;
    const __nv_bfloat16* gql = g_ql + ((long)b * Tz + q0) * Hz;
    for (int i = tid; i < 2048; i += 256) {
        int arr = i / 1024, idx = i % 1024;
        int r = idx / 8, ch = idx % 8;
        const __nv_bfloat16* src = arr ? gql : gqh;
        *(uint4*)(smem + arr * ARR + (uint32_t)(r * LDA + ch * 8) * 2) =
            *(const uint4*)(src + r * Hz + ch * 8);
    }
    __syncthreads();

    uint32_t qh[4][4], ql[4][4];
    #pragma unroll
    for (int kc = 0; kc < 4; kc++) {
        uint32_t aoff = (uint32_t)((wr0 + rr + (grp & 1) * 8) * LDA
                                   + kc * 16 + (grp >> 1) * 8) * 2;
        ldsm4(qh[kc], sb + 0 * ARR + aoff);
        ldsm4(ql[kc], sb + 1 * ARR + aoff);
    }
    __syncthreads();   // Q smem free for reuse

    float O[8][4] = {};
    float mrow[2] = {-1e30f, -1e30f};
    float lrow[2] = {0.0f, 0.0f};

    const __nv_bfloat16* gsrc[4] = {
        g_kh + (long)b * Tz * Hz, g_kl + (long)b * Tz * Hz,
        g_vh + (long)b * Tz * Hz, g_vl + (long)b * Tz * Hz};

    int njt = qt + 1;

    // prologue: stage tile 0 into buf0
    for (int i = tid; i < 4096; i += 256) {
        int arr = i >> 10, idx = i & 1023;
        int r = idx >> 3, ch = idx & 7;
        cp16(sb + arr * ARR + (uint32_t)(r * LDA + ch * 8) * 2,
             gsrc[arr] + (long)r * Hz + ch * 8);
    }
    cpcommit();

    for (int j = 0; j < njt; j++) {
        uint32_t bufc = (uint32_t)(j & 1) * BUFS;
        if (j + 1 < njt) {
            uint32_t bufn = (uint32_t)((j + 1) & 1) * BUFS;
            int jb = (j + 1) * 128;
            for (int i = tid; i < 4096; i += 256) {
                int arr = i >> 10, idx = i & 1023;
                int r = idx >> 3, ch = idx & 7;
                cp16(sb + bufn + arr * ARR + (uint32_t)(r * LDA + ch * 8) * 2,
                     gsrc[arr] + (long)(jb + r) * Hz + ch * 8);
            }
            cpcommit();
            cpwait<1>();
        } else {
            cpwait<0>();
        }
        __syncthreads();

        #pragma unroll
        for (int half = 0; half < 2; half++) {
            int kb = j * 128 + half * 64;
            if (kb > r0a + 15) break;      // fully masked for this warp
            uint32_t rbase = (uint32_t)(half * 64);

            // ---- S = Q K^T over 64 keys ----
            float S[8][4] = {};
            #pragma unroll
            for (int np = 0; np < 4; np++) {
                #pragma unroll
                for (int kc = 0; kc < 4; kc++) {
                    uint32_t row = rbase + np * 16 + ((grp >> 1) ? 8u : 0u) + rr;
                    uint32_t col = (uint32_t)(kc * 16 + (grp & 1) * 8);
                    uint32_t off = (row * LDA + col) * 2;
                    uint32_t bh[4], bl[4];
                    ldsm4(bh, sb + bufc + 0 * ARR + off);
                    ldsm4(bl, sb + bufc + 1 * ARR + off);
                    mma16816(S[np * 2], qh[kc], bh);
                    mma16816(S[np * 2], ql[kc], bh);
                    mma16816(S[np * 2], qh[kc], bl);
                    mma16816(S[np * 2 + 1], qh[kc], bh + 2);
                    mma16816(S[np * 2 + 1], ql[kc], bh + 2);
                    mma16816(S[np * 2 + 1], qh[kc], bl + 2);
                }
            }

            // ---- causal mask ----
            int rA = r0a + lane / 4;
            int rB = rA + 8;
            if (kb + 63 > r0a) {
                #pragma unroll
                for (int n = 0; n < 8; n++) {
                    int c0 = kb + n * 8 + 2 * (lane % 4);
                    if (c0 > rA)     S[n][0] = -1e30f;
                    if (c0 + 1 > rA) S[n][1] = -1e30f;
                    if (c0 > rB)     S[n][2] = -1e30f;
                    if (c0 + 1 > rB) S[n][3] = -1e30f;
                }
            }

            // ---- online softmax ----
            float mA = -1e30f, mB = -1e30f;
            #pragma unroll
            for (int n = 0; n < 8; n++) {
                mA = fmaxf(mA, fmaxf(S[n][0], S[n][1]));
                mB = fmaxf(mB, fmaxf(S[n][2], S[n][3]));
            }
            #pragma unroll
            for (int off = 1; off < 4; off <<= 1) {
                mA = fmaxf(mA, __shfl_xor_sync(0xffffffffu, mA, off));
                mB = fmaxf(mB, __shfl_xor_sync(0xffffffffu, mB, off));
            }
            float mnA = fmaxf(mrow[0], mA), mnB = fmaxf(mrow[1], mB);
            float aA = __expf(mrow[0] - mnA), aB = __expf(mrow[1] - mnB);
            mrow[0] = mnA; mrow[1] = mnB;
            float sA = 0.0f, sB = 0.0f;
            #pragma unroll
            for (int n = 0; n < 8; n++) {
                S[n][0] = __expf(S[n][0] - mnA); sA += S[n][0];
                S[n][1] = __expf(S[n][1] - mnA); sA += S[n][1];
                S[n][2] = __expf(S[n][2] - mnB); sB += S[n][2];
                S[n][3] = __expf(S[n][3] - mnB); sB += S[n][3];
            }
            #pragma unroll
            for (int off = 1; off < 4; off <<= 1) {
                sA += __shfl_xor_sync(0xffffffffu, sA, off);
                sB += __shfl_xor_sync(0xffffffffu, sB, off);
            }
            lrow[0] = lrow[0] * aA + sA;
            lrow[1] = lrow[1] * aB + sB;
            #pragma unroll
            for (int n = 0; n < 8; n++) {
                O[n][0] *= aA; O[n][1] *= aA; O[n][2] *= aB; O[n][3] *= aB;
            }

            // ---- O += P V ----
            #pragma unroll
            for (int kc = 0; kc < 4; kc++) {
                int t0 = 2 * kc, t1 = 2 * kc + 1;
                uint32_t ph[4], pl[4];
                split2(S[t0][0], S[t0][1], ph[0], pl[0]);
                split2(S[t0][2], S[t0][3], ph[1], pl[1]);
                split2(S[t1][0], S[t1][1], ph[2], pl[2]);
                split2(S[t1][2], S[t1][3], ph[3], pl[3]);
                #pragma unroll
                for (int np = 0; np < 4; np++) {
                    uint32_t row = rbase + kc * 16 + ((grp & 1) ? 8u : 0u) + rr;
                    uint32_t col = (uint32_t)(np * 16 + (grp >> 1) * 8);
                    uint32_t off = (row * LDA + col) * 2;
                    uint32_t vh[4], vl[4];
                    ldsm4t(vh, sb + bufc + 2 * ARR + off);
                    ldsm4t(vl, sb + bufc + 3 * ARR + off);
                    mma16816(O[np * 2], ph, vh);
                    mma16816(O[np * 2], pl, vh);
                    mma16816(O[np * 2], ph, vl);
                    mma16816(O[np * 2 + 1], ph, vh + 2);
                    mma16816(O[np * 2 + 1], pl, vh + 2);
                    mma16816(O[np * 2 + 1], ph, vl + 2);
                }
            }
        }
        __syncthreads();   // all warps done with bufc before refill
    }

    float invA = 1.0f / lrow[0];
    float invB = 1.0f / lrow[1];
    long rA = (long)b * Tz + r0a + lane / 4;
    long rB = rA + 8;
    int cb = 2 * (lane % 4);
    #pragma unroll
    for (int n = 0; n < 8; n++) {
        *(float2*)&out[rA * Hz + n * 8 + cb] =
            make_float2(O[n][0] * invA, O[n][1] * invA);
        *(float2*)&out[rB * Hz + n * 8 + cb] =
            make_float2(O[n][2] * invB, O[n][3] * invB);
    }
}

extern "C" void kernel_launch(void* const* d_in, const int* in_sizes, int n_in,
                              void* d_out, int out_size) {
    const float* x  = (const float*)d_in[0];
    const float* Wk = (const float*)d_in[1];
    const float* Wq = (const float*)d_in[2];
    const float* Wv = (const float*)d_in[3];
    float* out = (float*)d_out;

    prep_kernel<<<48, 256>>>(Wk, Wq, Wv);

    cudaFuncSetAttribute(proj_kernel,
                         cudaFuncAttributeMaxDynamicSharedMemorySize, PSMEM);
    dim3 pg((Bz * Tz) / 128, 3);
    proj_kernel<<<pg, 256, PSMEM>>>(x);

    cudaFuncSetAttribute(attn_kernel,
                         cudaFuncAttributeMaxDynamicSharedMemorySize, ASMEM);
    dim3 ag(Tz / 128, Bz);
    attn_kernel<<<ag, 256, ASMEM>>>(out);
}

// round 8
// speedup vs baseline: 3.4983x; 1.2421x over previous
#include <cuda_runtime.h>
#include <cuda_bf16.h>
#include <cstdint>
#include <stdint.h>
#include <math.h>

#define Bz 8
#define Tz 4096
#define Cz 768
#define Hz 64

// global scratch (allocation-free rule)
__device__ __nv_bfloat16 g_qh[Bz * Tz * Hz];
__device__ __nv_bfloat16 g_ql[Bz * Tz * Hz];
__device__ __nv_bfloat16 g_kh[Bz * Tz * Hz];
__device__ __nv_bfloat16 g_kl[Bz * Tz * Hz];
__device__ __nv_bfloat16 g_vh[Bz * Tz * Hz];
__device__ __nv_bfloat16 g_vl[Bz * Tz * Hz];
__device__ __nv_bfloat16 g_wth[3 * Hz * Cz];   // W^T hi  [mat][h][c]
__device__ __nv_bfloat16 g_wtl[3 * Hz * Cz];   // W^T lo

// ---------------------------------------------------------------------------
// helpers
// ---------------------------------------------------------------------------
__device__ __forceinline__ uint32_t smem_u32(const void* p) {
    uint32_t a;
    asm("{ .reg .u64 t; cvta.to.shared.u64 t, %1; cvt.u32.u64 %0, t; }"
        : "=r"(a) : "l"(p));
    return a;
}
__device__ __forceinline__ void ldsm4(uint32_t* r, uint32_t a) {
    asm volatile("ldmatrix.sync.aligned.m8n8.x4.shared.b16 {%0,%1,%2,%3}, [%4];"
        : "=r"(r[0]), "=r"(r[1]), "=r"(r[2]), "=r"(r[3]) : "r"(a));
}
__device__ __forceinline__ void ldsm4t(uint32_t* r, uint32_t a) {
    asm volatile("ldmatrix.sync.aligned.m8n8.x4.trans.shared.b16 {%0,%1,%2,%3}, [%4];"
        : "=r"(r[0]), "=r"(r[1]), "=r"(r[2]), "=r"(r[3]) : "r"(a));
}
__device__ __forceinline__ void ldsm2(uint32_t* r, uint32_t a) {
    asm volatile("ldmatrix.sync.aligned.m8n8.x2.shared.b16 {%0,%1}, [%2];"
        : "=r"(r[0]), "=r"(r[1]) : "r"(a));
}
__device__ __forceinline__ void mma16816(float* d, const uint32_t* a,
                                         const uint32_t* b) {
    asm volatile(
        "mma.sync.aligned.m16n8k16.row.col.f32.bf16.bf16.f32 "
        "{%0,%1,%2,%3}, {%4,%5,%6,%7}, {%8,%9}, {%0,%1,%2,%3};"
        : "+f"(d[0]), "+f"(d[1]), "+f"(d[2]), "+f"(d[3])
        : "r"(a[0]), "r"(a[1]), "r"(a[2]), "r"(a[3]), "r"(b[0]), "r"(b[1]));
}
__device__ __forceinline__ void cp16(uint32_t dst, const void* src) {
    asm volatile("cp.async.cg.shared.global [%0], [%1], 16;"
                 :: "r"(dst), "l"(src) : "memory");
}
__device__ __forceinline__ void cpcommit() {
    asm volatile("cp.async.commit_group;" ::: "memory");
}
template <int N> __device__ __forceinline__ void cpwait() {
    asm volatile("cp.async.wait_group %0;" :: "n"(N) : "memory");
}

// split two floats into packed bf16x2 hi + lo residual
__device__ __forceinline__ void split2(float f0, float f1,
                                       uint32_t& hi, uint32_t& lo) {
    __nv_bfloat162 h = __floats2bfloat162_rn(f0, f1);
    float g0 = __low2float(h), g1 = __high2float(h);
    __nv_bfloat162 l = __floats2bfloat162_rn(f0 - g0, f1 - g1);
    hi = reinterpret_cast<uint32_t&>(h);
    lo = reinterpret_cast<uint32_t&>(l);
}
__device__ __forceinline__ void splits(float v, __nv_bfloat16& hi,
                                       __nv_bfloat16& lo) {
    hi = __float2bfloat16(v);
    lo = __float2bfloat16(v - __bfloat162float(hi));
}

// ---------------------------------------------------------------------------
// prep: W -> W^T bf16 hi/lo   grid(48): mat = bx/16, slice = bx%16
// ---------------------------------------------------------------------------
__global__ void prep_kernel(const float* __restrict__ Wk,
                            const float* __restrict__ Wq,
                            const float* __restrict__ Wv) {
    int mat = blockIdx.x / 16;
    int slice = blockIdx.x % 16;
    const float* W = (mat == 0) ? Wq : ((mat == 1) ? Wk : Wv);
    int n = Cz * Hz / 16;
    int base = slice * n;
    for (int t = threadIdx.x; t < n; t += 256) {
        int i = base + t;
        int c = i / Hz, h = i % Hz;
        __nv_bfloat16 hi, lo;
        splits(W[i], hi, lo);
        g_wth[mat * Hz * Cz + h * Cz + c] = hi;
        g_wtl[mat * Hz * Cz + h * Cz + c] = lo;
    }
}

// ---------------------------------------------------------------------------
// projection: all 3 matrices per block; x staged/converted ONCE per k-chunk.
// grid (256), 256 threads, 8 warps x 16 rows, k-chunks of 64
// smem: x hi/lo [128x72] + per-mat W hi/lo [64x72]
// ---------------------------------------------------------------------------
#define PLD 72
#define PXH 0
#define PXL 18432
#define PW  36864            // + mat*18432 (hi), +9216 (lo)
#define PSMEM (36864 + 3 * 18432)   // 92160

__global__ void __launch_bounds__(256) proj_kernel(const float* __restrict__ x) {
    extern __shared__ char smem[];
    uint32_t sb = smem_u32(smem);

    long row0 = (long)blockIdx.x * 128;
    int tid = threadIdx.x, wid = tid / 32, lane = tid % 32;
    int wr0 = wid * 16;
    int rr = lane % 8, grp = lane / 8;

    float acc[3][8][4] = {};

    for (int it = 0; it < 12; it++) {
        int k0 = it * 64;
        __syncthreads();
        // stage x hi/lo (once for all 3 mats)
        for (int i = tid; i < 128 * 16; i += 256) {
            int r = i / 16, c4 = (i % 16) * 4;
            float4 xv = *(const float4*)&x[(row0 + r) * Cz + k0 + c4];
            uint32_t h0, l0, h1, l1;
            split2(xv.x, xv.y, h0, l0);
            split2(xv.z, xv.w, h1, l1);
            uint32_t off = (uint32_t)(r * PLD + c4) * 2;
            *(uint2*)(smem + PXH + off) = make_uint2(h0, h1);
            *(uint2*)(smem + PXL + off) = make_uint2(l0, l1);
        }
        // stage W^T hi/lo for all 3 mats
        for (int i = tid; i < 3 * 64 * 8; i += 256) {
            int mat = i / 512, rem = i % 512;
            int h = rem / 8, ch = rem % 8;
            uint32_t off = PW + mat * 18432 + (uint32_t)(h * PLD + ch * 8) * 2;
            *(uint4*)(smem + off) =
                *(const uint4*)(g_wth + mat * Hz * Cz + h * Cz + k0 + ch * 8);
            *(uint4*)(smem + off + 9216) =
                *(const uint4*)(g_wtl + mat * Hz * Cz + h * Cz + k0 + ch * 8);
        }
        __syncthreads();

        #pragma unroll
        for (int kc = 0; kc < 4; kc++) {
            uint32_t ah[4], al[4];
            uint32_t aoff = (uint32_t)((wr0 + rr + (grp & 1) * 8) * PLD
                                       + kc * 16 + (grp >> 1) * 8) * 2;
            ldsm4(ah, sb + PXH + aoff);
            ldsm4(al, sb + PXL + aoff);
            #pragma unroll
            for (int mat = 0; mat < 3; mat++) {
                uint32_t wb = sb + PW + (uint32_t)mat * 18432;
                #pragma unroll
                for (int n = 0; n < 8; n++) {
                    uint32_t bh[2], bl[2];
                    uint32_t boff = (uint32_t)((n * 8 + rr) * PLD
                                               + kc * 16 + (grp & 1) * 8) * 2;
                    ldsm2(bh, wb + boff);
                    ldsm2(bl, wb + 9216 + boff);
                    mma16816(acc[mat][n], ah, bh);
                    mma16816(acc[mat][n], ah, bl);
                    mma16816(acc[mat][n], al, bh);
                }
            }
        }
    }

    long rA = row0 + wr0 + lane / 4;
    long rB = rA + 8;
    int cb = 2 * (lane % 4);
    #pragma unroll
    for (int mat = 0; mat < 3; mat++) {
        __nv_bfloat16* outh = (mat == 0) ? g_qh : ((mat == 1) ? g_kh : g_vh);
        __nv_bfloat16* outl = (mat == 0) ? g_ql : ((mat == 1) ? g_kl : g_vl);
        float scale = (mat == 0) ? 0.03608439182435161f : 1.0f;
        #pragma unroll
        for (int n = 0; n < 8; n++) {
            uint32_t hi, lo;
            split2(acc[mat][n][0] * scale, acc[mat][n][1] * scale, hi, lo);
            *(uint32_t*)&outh[rA * Hz + n * 8 + cb] = hi;
            *(uint32_t*)&outl[rA * Hz + n * 8 + cb] = lo;
            split2(acc[mat][n][2] * scale, acc[mat][n][3] * scale, hi, lo);
            *(uint32_t*)&outh[rB * Hz + n * 8 + cb] = hi;
            *(uint32_t*)&outl[rB * Hz + n * 8 + cb] = lo;
        }
    }
}

// ---------------------------------------------------------------------------
// flash attention: q-tile 128, k-tile 128 (2 x 64 halves), cp.async double buf
// grid (16, 8): block bx handles q-tiles {bx, 31-bx} -> 33 steps each,
// one perfectly balanced wave of 128 blocks.
// ---------------------------------------------------------------------------
#define LDA 72
#define ARR 18432                       // one 128x72 half-array (bytes)
#define BUFS 73728                      // 4 arrays (Kh,Kl,Vh,Vl)
#define ASMEM (2 * BUFS)                // 147456

__global__ void __launch_bounds__(256) attn_kernel(float* __restrict__ out) {
    extern __shared__ char smem[];
    uint32_t sb = smem_u32(smem);

    int tid = threadIdx.x, wid = tid / 32, lane = tid % 32;
    int b = blockIdx.y;
    int rr = lane % 8, grp = lane / 8;
    int wr0 = wid * 16;

    const __nv_bfloat16* gsrc[4] = {
        g_kh + (long)b * Tz * Hz, g_kl + (long)b * Tz * Hz,
        g_vh + (long)b * Tz * Hz, g_vl + (long)b * Tz * Hz};

    for (int wh = 0; wh < 2; wh++) {
        int qt = wh ? (31 - (int)blockIdx.x) : (int)blockIdx.x;
        int q0 = qt * 128;
        int r0a = q0 + wr0;

        // ---- stage Q (into buf0 slots 0/1, then freed) ----
        const __nv_bfloat16* gqh = g_qh + ((long)b * Tz + q0) * Hz;
        const __nv_bfloat16* gql = g_ql + ((long)b * Tz + q0) * Hz;
        for (int i = tid; i < 2048; i += 256) {
            int arr = i / 1024, idx = i % 1024;
            int r = idx / 8, ch = idx % 8;
            const __nv_bfloat16* src = arr ? gql : gqh;
            *(uint4*)(smem + arr * ARR + (uint32_t)(r * LDA + ch * 8) * 2) =
                *(const uint4*)(src + r * Hz + ch * 8);
        }
        __syncthreads();

        uint32_t qh[4][4], ql[4][4];
        #pragma unroll
        for (int kc = 0; kc < 4; kc++) {
            uint32_t aoff = (uint32_t)((wr0 + rr + (grp & 1) * 8) * LDA
                                       + kc * 16 + (grp >> 1) * 8) * 2;
            ldsm4(qh[kc], sb + 0 * ARR + aoff);
            ldsm4(ql[kc], sb + 1 * ARR + aoff);
        }
        __syncthreads();   // Q smem free for reuse

        float O[8][4] = {};
        float mrow[2] = {-1e30f, -1e30f};
        float lrow[2] = {0.0f, 0.0f};

        int njt = qt + 1;

        // prologue: stage tile 0 into buf0
        for (int i = tid; i < 4096; i += 256) {
            int arr = i >> 10, idx = i & 1023;
            int r = idx >> 3, ch = idx & 7;
            cp16(sb + arr * ARR + (uint32_t)(r * LDA + ch * 8) * 2,
                 gsrc[arr] + (long)r * Hz + ch * 8);
        }
        cpcommit();

        for (int j = 0; j < njt; j++) {
            uint32_t bufc = (uint32_t)(j & 1) * BUFS;
            if (j + 1 < njt) {
                uint32_t bufn = (uint32_t)((j + 1) & 1) * BUFS;
                int jb = (j + 1) * 128;
                for (int i = tid; i < 4096; i += 256) {
                    int arr = i >> 10, idx = i & 1023;
                    int r = idx >> 3, ch = idx & 7;
                    cp16(sb + bufn + arr * ARR + (uint32_t)(r * LDA + ch * 8) * 2,
                         gsrc[arr] + (long)(jb + r) * Hz + ch * 8);
                }
                cpcommit();
                cpwait<1>();
            } else {
                cpwait<0>();
            }
            __syncthreads();

            #pragma unroll
            for (int half = 0; half < 2; half++) {
                int kb = j * 128 + half * 64;
                if (kb > r0a + 15) break;      // fully masked for this warp
                uint32_t rbase = (uint32_t)(half * 64);

                // ---- S = Q K^T over 64 keys ----
                float S[8][4] = {};
                #pragma unroll
                for (int np = 0; np < 4; np++) {
                    #pragma unroll
                    for (int kc = 0; kc < 4; kc++) {
                        uint32_t row = rbase + np * 16 + ((grp >> 1) ? 8u : 0u) + rr;
                        uint32_t col = (uint32_t)(kc * 16 + (grp & 1) * 8);
                        uint32_t off = (row * LDA + col) * 2;
                        uint32_t bh[4], bl[4];
                        ldsm4(bh, sb + bufc + 0 * ARR + off);
                        ldsm4(bl, sb + bufc + 1 * ARR + off);
                        mma16816(S[np * 2], qh[kc], bh);
                        mma16816(S[np * 2], ql[kc], bh);
                        mma16816(S[np * 2], qh[kc], bl);
                        mma16816(S[np * 2 + 1], qh[kc], bh + 2);
                        mma16816(S[np * 2 + 1], ql[kc], bh + 2);
                        mma16816(S[np * 2 + 1], qh[kc], bl + 2);
                    }
                }

                // ---- causal mask ----
                int rA = r0a + lane / 4;
                int rB = rA + 8;
                if (kb + 63 > r0a) {
                    #pragma unroll
                    for (int n = 0; n < 8; n++) {
                        int c0 = kb + n * 8 + 2 * (lane % 4);
                        if (c0 > rA)     S[n][0] = -1e30f;
                        if (c0 + 1 > rA) S[n][1] = -1e30f;
                        if (c0 > rB)     S[n][2] = -1e30f;
                        if (c0 + 1 > rB) S[n][3] = -1e30f;
                    }
                }

                // ---- online softmax ----
                float mA = -1e30f, mB = -1e30f;
                #pragma unroll
                for (int n = 0; n < 8; n++) {
                    mA = fmaxf(mA, fmaxf(S[n][0], S[n][1]));
                    mB = fmaxf(mB, fmaxf(S[n][2], S[n][3]));
                }
                #pragma unroll
                for (int off = 1; off < 4; off <<= 1) {
                    mA = fmaxf(mA, __shfl_xor_sync(0xffffffffu, mA, off));
                    mB = fmaxf(mB, __shfl_xor_sync(0xffffffffu, mB, off));
                }
                float mnA = fmaxf(mrow[0], mA), mnB = fmaxf(mrow[1], mB);
                float aA = __expf(mrow[0] - mnA), aB = __expf(mrow[1] - mnB);
                mrow[0] = mnA; mrow[1] = mnB;
                float sA = 0.0f, sB = 0.0f;
                #pragma unroll
                for (int n = 0; n < 8; n++) {
                    S[n][0] = __expf(S[n][0] - mnA); sA += S[n][0];
                    S[n][1] = __expf(S[n][1] - mnA); sA += S[n][1];
                    S[n][2] = __expf(S[n][2] - mnB); sB += S[n][2];
                    S[n][3] = __expf(S[n][3] - mnB); sB += S[n][3];
                }
                #pragma unroll
                for (int off = 1; off < 4; off <<= 1) {
                    sA += __shfl_xor_sync(0xffffffffu, sA, off);
                    sB += __shfl_xor_sync(0xffffffffu, sB, off);
                }
                lrow[0] = lrow[0] * aA + sA;
                lrow[1] = lrow[1] * aB + sB;
                #pragma unroll
                for (int n = 0; n < 8; n++) {
                    O[n][0] *= aA; O[n][1] *= aA; O[n][2] *= aB; O[n][3] *= aB;
                }

                // ---- O += P V ----
                #pragma unroll
                for (int kc = 0; kc < 4; kc++) {
                    int t0 = 2 * kc, t1 = 2 * kc + 1;
                    uint32_t ph[4], pl[4];
                    split2(S[t0][0], S[t0][1], ph[0], pl[0]);
                    split2(S[t0][2], S[t0][3], ph[1], pl[1]);
                    split2(S[t1][0], S[t1][1], ph[2], pl[2]);
                    split2(S[t1][2], S[t1][3], ph[3], pl[3]);
                    #pragma unroll
                    for (int np = 0; np < 4; np++) {
                        uint32_t row = rbase + kc * 16 + ((grp & 1) ? 8u : 0u) + rr;
                        uint32_t col = (uint32_t)(np * 16 + (grp >> 1) * 8);
                        uint32_t off = (row * LDA + col) * 2;
                        uint32_t vh[4], vl[4];
                        ldsm4t(vh, sb + bufc + 2 * ARR + off);
                        ldsm4t(vl, sb + bufc + 3 * ARR + off);
                        mma16816(O[np * 2], ph, vh);
                        mma16816(O[np * 2], pl, vh);
                        mma16816(O[np * 2], ph, vl);
                        mma16816(O[np * 2 + 1], ph, vh + 2);
                        mma16816(O[np * 2 + 1], pl, vh + 2);
                        mma16816(O[np * 2 + 1], ph, vl + 2);
                    }
                }
            }
            __syncthreads();   // all warps done with bufc before refill
        }

        // epilogue for this q-tile
        float invA = 1.0f / lrow[0];
        float invB = 1.0f / lrow[1];
        long rA = (long)b * Tz + r0a + lane / 4;
        long rB = rA + 8;
        int cb = 2 * (lane % 4);
        #pragma unroll
        for (int n = 0; n < 8; n++) {
            *(float2*)&out[rA * Hz + n * 8 + cb] =
                make_float2(O[n][0] * invA, O[n][1] * invA);
            *(float2*)&out[rB * Hz + n * 8 + cb] =
                make_float2(O[n][2] * invB, O[n][3] * invB);
        }
        __syncthreads();   // done with all smem before next q-tile restages Q
    }
}

extern "C" void kernel_launch(void* const* d_in, const int* in_sizes, int n_in,
                              void* d_out, int out_size) {
    const float* x  = (const float*)d_in[0];
    const float* Wk = (const float*)d_in[1];
    const float* Wq = (const float*)d_in[2];
    const float* Wv = (const float*)d_in[3];
    float* out = (float*)d_out;

    prep_kernel<<<48, 256>>>(Wk, Wq, Wv);

    cudaFuncSetAttribute(proj_kernel,
                         cudaFuncAttributeMaxDynamicSharedMemorySize, PSMEM);
    proj_kernel<<<(Bz * Tz) / 128, 256, PSMEM>>>(x);

    cudaFuncSetAttribute(attn_kernel,
                         cudaFuncAttributeMaxDynamicSharedMemorySize, ASMEM);
    dim3 ag(Tz / 256, Bz);
    attn_kernel<<<ag, 256, ASMEM>>>(out);
}